// round 10
// baseline (speedup 1.0000x reference)
#include <cuda_runtime.h>
#include <cuda_bf16.h>
#include <cstdint>

// causal softmax(QK^T/sqrt(64)): q,k [48,2048,64] fp32 -> out [48,2048,2048] fp32
//
// ONE mega-kernel, phases by bid range (in-order dispatch => waits only target
// lower bids => deadlock-free):
//   [0,768)    prep_q : q -> bf16 hi/lo A-fragment scratch; post qprep[bh*16+qb]
//   [768,1536) prep_k : k -> bf16 hi/lo swizzled tile images; post kprep[bh] (x16)
//   [1536,4608) sum   : wait preps(bh) -> MMA (1-split bf16, 3-split for qb==0)
//                       + exp -> partial row sums; post g_flag[bh*16+qb];
//                       then upper-triangle zero-fill.
//   [4608,7680) store : wait preps -> prefetch -> wait g_flag>=nchunks ->
//                       3-split MMA, exp, normalize, coalesced stores.
// A tiny reset kernel zeroes the flag arrays each call (replay safety).
// Non-contributing partial slots are never written non-zero => no reset needed.

#define TT 2048
#define NBH 48

__device__ __align__(16) char g_qf[(size_t)NBH * 16 * 32768];  // [bh][qb]: hi 16KB | lo 16KB
__device__ __align__(16) char g_ki[(size_t)NBH * 32 * 16384];  // [bh][t64]: hi 8KB | lo 8KB
__device__ float g_part[NBH * 16 * 4 * 128];                   // [bh][qb][chunk][row]
__device__ unsigned g_flag[NBH * 16];                          // sum chunks done per (bh,qb)
__device__ unsigned g_qprep[NBH * 16];                         // q prep done per (bh,qb)
__device__ unsigned g_kprep[NBH];                              // k prep sub-CTAs done per bh

#define SMEM_BYTES (3 * 16384)

__device__ __forceinline__ uint32_t smem_u32(const void* p) {
    uint32_t a;
    asm("{ .reg .u64 t; cvta.to.shared.u64 t, %1; cvt.u32.u64 %0, t; }" : "=r"(a) : "l"(p));
    return a;
}
__device__ __forceinline__ void ldsm_x4(uint32_t r[4], uint32_t addr) {
    asm volatile("ldmatrix.sync.aligned.m8n8.x4.shared.b16 {%0,%1,%2,%3}, [%4];"
        : "=r"(r[0]), "=r"(r[1]), "=r"(r[2]), "=r"(r[3]) : "r"(addr));
}
__device__ __forceinline__ void mma16816(float c[4], const uint32_t a[4], const uint32_t b[2]) {
    asm volatile("mma.sync.aligned.m16n8k16.row.col.f32.bf16.bf16.f32 "
        "{%0,%1,%2,%3}, {%4,%5,%6,%7}, {%8,%9}, {%0,%1,%2,%3};"
        : "+f"(c[0]), "+f"(c[1]), "+f"(c[2]), "+f"(c[3])
        : "r"(a[0]), "r"(a[1]), "r"(a[2]), "r"(a[3]), "r"(b[0]), "r"(b[1]));
}
#define CP_ASYNC16(sa, gp) \
    asm volatile("cp.async.cg.shared.global [%0], [%1], 16;" :: "r"(sa), "l"(gp))
#define CP_COMMIT() asm volatile("cp.async.commit_group;")
#define CP_WAIT2()  asm volatile("cp.async.wait_group 2;")

__device__ __forceinline__ void split2(float x, float y, uint32_t& h, uint32_t& l) {
    __nv_bfloat16 hx = __float2bfloat16(x);
    __nv_bfloat16 hy = __float2bfloat16(y);
    __nv_bfloat162 hv; hv.x = hx; hv.y = hy;
    __nv_bfloat162 lv;
    lv.x = __float2bfloat16(x - __bfloat162float(hx));
    lv.y = __float2bfloat16(y - __bfloat162float(hy));
    h = *reinterpret_cast<uint32_t*>(&hv);
    l = *reinterpret_cast<uint32_t*>(&lv);
}

__device__ __forceinline__ void wait_flag(const unsigned* p, unsigned target) {
    unsigned v;
    do {
        asm volatile("ld.acquire.gpu.global.b32 %0, [%1];" : "=r"(v) : "l"(p) : "memory");
        if (v >= target) return;
        __nanosleep(64);
    } while (true);
}

__device__ __forceinline__ void load_afrags(const char* src, int w, int lane,
                                            uint32_t ah[2][4][4], uint32_t al[2][4][4])
{
    #pragma unroll
    for (int r2 = 0; r2 < 2; r2++) {
        const int g = (w << 1) + r2;
        #pragma unroll
        for (int kc = 0; kc < 4; kc++) {
            const uint32_t a = (uint32_t)(((((g << 2) + kc) << 5) + lane) << 4);
            const uint4 h = *(const uint4*)(src + a);
            ah[r2][kc][0] = h.x; ah[r2][kc][1] = h.y; ah[r2][kc][2] = h.z; ah[r2][kc][3] = h.w;
            const uint4 l = *(const uint4*)(src + 16384 + a);
            al[r2][kc][0] = l.x; al[r2][kc][1] = l.y; al[r2][kc][2] = l.z; al[r2][kc][3] = l.w;
        }
    }
}

__device__ __forceinline__ void issue_tile(uint32_t sb, int stage, const char* src,
                                           int tid, bool with_lo)
{
    const uint32_t dst = sb + ((uint32_t)stage << 14) + ((uint32_t)tid << 4);
    const char* s = src + (tid << 4);
    #pragma unroll
    for (int i = 0; i < 4; i++)
        CP_ASYNC16(dst + (i << 11), s + (i << 11));
    if (with_lo) {
        #pragma unroll
        for (int i = 4; i < 8; i++)
            CP_ASYNC16(dst + (i << 11), s + (i << 11));
    }
}

__device__ __forceinline__ void mma_tile3(uint32_t nbase, const uint32_t bOff[4],
                                          const uint32_t ah[2][4][4], const uint32_t al[2][4][4],
                                          float a00[4], float a01[4], float a10[4], float a11[4])
{
    #pragma unroll
    for (int kc = 0; kc < 4; kc++) {
        uint32_t bhr[4], blr[4];
        ldsm_x4(bhr, nbase + bOff[kc]);
        ldsm_x4(blr, nbase + 8192 + bOff[kc]);
        mma16816(a00, ah[0][kc], &bhr[0]);
        mma16816(a01, ah[0][kc], &bhr[2]);
        mma16816(a10, ah[1][kc], &bhr[0]);
        mma16816(a11, ah[1][kc], &bhr[2]);
        mma16816(a00, ah[0][kc], &blr[0]);
        mma16816(a01, ah[0][kc], &blr[2]);
        mma16816(a10, ah[1][kc], &blr[0]);
        mma16816(a11, ah[1][kc], &blr[2]);
        mma16816(a00, al[0][kc], &bhr[0]);
        mma16816(a01, al[0][kc], &bhr[2]);
        mma16816(a10, al[1][kc], &bhr[0]);
        mma16816(a11, al[1][kc], &bhr[2]);
    }
}

__device__ __forceinline__ void mma_tile1(uint32_t nbase, const uint32_t bOff[4],
                                          const uint32_t ah[2][4][4],
                                          float a00[4], float a01[4], float a10[4], float a11[4])
{
    #pragma unroll
    for (int kc = 0; kc < 4; kc++) {
        uint32_t bhr[4];
        ldsm_x4(bhr, nbase + bOff[kc]);
        mma16816(a00, ah[0][kc], &bhr[0]);
        mma16816(a01, ah[0][kc], &bhr[2]);
        mma16816(a10, ah[1][kc], &bhr[0]);
        mma16816(a11, ah[1][kc], &bhr[2]);
    }
}

// ---------------- reset (replay safety) ----------------
__global__ void reset_flags()
{
    const int t = threadIdx.x;
    #pragma unroll
    for (int j = 0; j < 3; j++) {
        const int i = t + j * 256;
        if (i < NBH * 16) { g_flag[i] = 0u; g_qprep[i] = 0u; }
    }
    if (t < NBH) g_kprep[t] = 0u;
}

// ---------------- mega kernel ----------------
__global__ void __launch_bounds__(128, 4)
sdp_mega(const float* __restrict__ qg, const float* __restrict__ kg,
         float* __restrict__ outg)
{
    extern __shared__ char smem[];
    const uint32_t sb = smem_u32(smem);
    const int tid = threadIdx.x, w = tid >> 5, lane = tid & 31;
    int bid = (int)blockIdx.x;

    // =================== PREP_Q ===================
    if (bid < 768) {
        const int qb = bid & 15, bh = bid >> 4;
        const float* qptr = qg + ((size_t)bh * TT + (qb << 7)) * 64;
        #pragma unroll
        for (int i = 0; i < 8; i++) {
            const int idx = tid + (i << 7);
            const int r = idx >> 3, c = idx & 7;
            const float* p = qptr + r * 64 + (c << 3);
            float4 v0 = *(const float4*)p;
            float4 v1 = *(const float4*)(p + 4);
            v0.x *= 0.125f; v0.y *= 0.125f; v0.z *= 0.125f; v0.w *= 0.125f;
            v1.x *= 0.125f; v1.y *= 0.125f; v1.z *= 0.125f; v1.w *= 0.125f;
            uint4 h, l;
            split2(v0.x, v0.y, h.x, l.x);
            split2(v0.z, v0.w, h.y, l.y);
            split2(v1.x, v1.y, h.z, l.z);
            split2(v1.z, v1.w, h.w, l.w);
            const uint32_t off = (r << 7) + (((uint32_t)c ^ (r & 7)) << 4);
            *(uint4*)(smem + off) = h;
            *(uint4*)(smem + 16384 + off) = l;
        }
        __syncthreads();

        uint32_t ah[2][4][4], al[2][4][4];
        const int cpar = lane >> 4;
        #pragma unroll
        for (int r2 = 0; r2 < 2; r2++) {
            const int rA = (w << 5) + (r2 << 4) + (lane & 15);
            #pragma unroll
            for (int kc = 0; kc < 4; kc++) {
                const uint32_t off = (uint32_t)(rA << 7)
                                   + (((uint32_t)((kc << 1) + cpar) ^ (rA & 7)) << 4);
                ldsm_x4(ah[r2][kc], sb + off);
                ldsm_x4(al[r2][kc], sb + 16384 + off);
            }
        }
        char* dst = g_qf + ((size_t)((bh << 4) + qb) << 15);
        #pragma unroll
        for (int r2 = 0; r2 < 2; r2++) {
            const int g = (w << 1) + r2;
            #pragma unroll
            for (int kc = 0; kc < 4; kc++) {
                const uint32_t a = (uint32_t)(((((g << 2) + kc) << 5) + lane) << 4);
                *(uint4*)(dst + a) =
                    make_uint4(ah[r2][kc][0], ah[r2][kc][1], ah[r2][kc][2], ah[r2][kc][3]);
                *(uint4*)(dst + 16384 + a) =
                    make_uint4(al[r2][kc][0], al[r2][kc][1], al[r2][kc][2], al[r2][kc][3]);
            }
        }
        __threadfence();
        __syncthreads();
        if (tid == 0) atomicAdd(&g_qprep[(bh << 4) + qb], 1u);
        return;
    }
    bid -= 768;

    // =================== PREP_K ===================
    if (bid < 768) {
        const int is = bid & 15, bh = bid >> 4;
        #pragma unroll
        for (int tt2 = 0; tt2 < 2; tt2++) {
            const int tt = (is << 1) + tt2;               // t64 0..31
            #pragma unroll
            for (int j = 0; j < 4; j++) {
                const int cidx = tid + (j << 7);          // 0..511
                const int row = cidx >> 3, c = cidx & 7;
                const int kgr = ((bh << 5) + tt) * 64 + row;
                const float* p = kg + (size_t)kgr * 64 + (c << 3);
                const float4 v0 = *(const float4*)p;
                const float4 v1 = *(const float4*)(p + 4);
                uint4 h, l;
                split2(v0.x, v0.y, h.x, l.x);
                split2(v0.z, v0.w, h.y, l.y);
                split2(v1.x, v1.y, h.z, l.z);
                split2(v1.z, v1.w, h.w, l.w);
                const size_t off = ((size_t)((bh << 5) + tt) << 14)
                                 + (uint32_t)(row * 128)
                                 + (((uint32_t)c ^ (row & 7)) << 4);
                *(uint4*)(g_ki + off) = h;
                *(uint4*)(g_ki + off + 8192) = l;
            }
        }
        __threadfence();
        __syncthreads();
        if (tid == 0) atomicAdd(&g_kprep[bh], 1u);
        return;
    }
    bid -= 768;

    // =================== SUM / STORE ===================
    const bool is_store = (bid >= 3072);
    if (is_store) bid -= 3072;
    const int ch = bid & 3;
    const int qb = 15 - ((bid >> 2) & 15);
    const int bh = bid >> 6;
    const int t_lo = ch << 3;
    const int dlim = 2 * qb + 1;
    const int q0 = qb << 7;
    const int nchunks = (dlim >> 3) + 1;
    const int fidx = (bh << 4) + qb;
    float* outp = outg + (size_t)bh * TT * TT;

    if (is_store && t_lo > dlim) return;

    const bool has_mma = (t_lo <= dlim);
    const int t_hi = min(t_lo + 7, dlim);
    const int nm = has_mma ? (t_hi - t_lo + 1) : 0;
    const bool full = is_store || (qb == 0);

    uint32_t ah[2][4][4], al[2][4][4];
    const int rowB  = (lane & 7) + ((lane >> 4) << 3);
    const int cparB = (lane >> 3) & 1;
    uint32_t bOff[4];
    #pragma unroll
    for (int kc = 0; kc < 4; kc++)
        bOff[kc] = (uint32_t)(rowB << 7)
                 + (((uint32_t)((kc << 1) + cparB) ^ (rowB & 7)) << 4);
    const int cbase = (lane & 3) << 1;
    int lr[2], grow0[2], grow1[2];
    #pragma unroll
    for (int r2 = 0; r2 < 2; r2++) {
        lr[r2] = (w << 5) + (r2 << 4) + (lane >> 2);
        grow0[r2] = q0 + lr[r2];
        grow1[r2] = grow0[r2] + 8;
    }

    const char* kb = g_ki + ((size_t)(bh * 32 + t_lo) << 14);

    if (has_mma) {
        // wait for this bh's preps (earlier bids only -> deadlock-free)
        if (tid == 0) {
            wait_flag(&g_qprep[fidx], 1u);
            wait_flag(&g_kprep[bh], 16u);
        }
        __syncthreads();
        load_afrags(g_qf + ((size_t)fidx << 15), w, lane, ah, al);
        #pragma unroll
        for (int p = 0; p < 3; p++) {
            if (p < nm) issue_tile(sb, p, kb + ((size_t)p << 14), tid, full);
            CP_COMMIT();
        }
    }

    if (!is_store) {
        // =================== SUM PHASE ===================
        if (has_mma) {
            float s0[2] = {0.f, 0.f}, s1[2] = {0.f, 0.f};
            #pragma unroll 1
            for (int i = 0; i < nm; i++) {
                CP_WAIT2();
                __syncthreads();
                const uint32_t stg = sb + ((uint32_t)(i % 3) << 14);
                const int tg = t_lo + i;
                const bool msk = (tg >= 2 * qb);
                #pragma unroll 1
                for (int nfp = 0; nfp < 4; nfp++) {
                    float a00[4] = {0,0,0,0}, a01[4] = {0,0,0,0};
                    float a10[4] = {0,0,0,0}, a11[4] = {0,0,0,0};
                    const uint32_t nbase = stg + ((uint32_t)nfp << 11);
                    if (full) mma_tile3(nbase, bOff, ah, al, a00, a01, a10, a11);
                    else      mma_tile1(nbase, bOff, ah,     a00, a01, a10, a11);

                    const int c0 = (tg << 6) + (nfp << 4) + cbase;
                    #pragma unroll
                    for (int r2 = 0; r2 < 2; r2++) {
                        float* accA = r2 ? a10 : a00;
                        float* accB = r2 ? a11 : a01;
                        if (!msk) {
                            s0[r2] += __expf(accA[0]) + __expf(accA[1])
                                    + __expf(accB[0]) + __expf(accB[1]);
                            s1[r2] += __expf(accA[2]) + __expf(accA[3])
                                    + __expf(accB[2]) + __expf(accB[3]);
                        } else {
                            if (c0     <= grow0[r2]) s0[r2] += __expf(accA[0]);
                            if (c0 + 1 <= grow0[r2]) s0[r2] += __expf(accA[1]);
                            if (c0 + 8 <= grow0[r2]) s0[r2] += __expf(accB[0]);
                            if (c0 + 9 <= grow0[r2]) s0[r2] += __expf(accB[1]);
                            if (c0     <= grow1[r2]) s1[r2] += __expf(accA[2]);
                            if (c0 + 1 <= grow1[r2]) s1[r2] += __expf(accA[3]);
                            if (c0 + 8 <= grow1[r2]) s1[r2] += __expf(accB[2]);
                            if (c0 + 9 <= grow1[r2]) s1[r2] += __expf(accB[3]);
                        }
                    }
                }
                __syncthreads();
                if (i + 3 < nm) issue_tile(sb, (i + 3) % 3, kb + ((size_t)(i + 3) << 14), tid, full);
                CP_COMMIT();
            }

            #pragma unroll
            for (int r2 = 0; r2 < 2; r2++) {
                s0[r2] += __shfl_xor_sync(0xffffffffu, s0[r2], 1);
                s0[r2] += __shfl_xor_sync(0xffffffffu, s0[r2], 2);
                s1[r2] += __shfl_xor_sync(0xffffffffu, s1[r2], 1);
                s1[r2] += __shfl_xor_sync(0xffffffffu, s1[r2], 2);
            }
            if ((lane & 3) == 0) {
                float* pp = g_part + (size_t)(((fidx << 2) + ch) << 7);
                #pragma unroll
                for (int r2 = 0; r2 < 2; r2++) {
                    pp[lr[r2]]     = s0[r2];
                    pp[lr[r2] + 8] = s1[r2];
                }
            }
            __threadfence();
            __syncthreads();
            if (tid == 0) atomicAdd(&g_flag[fidx], 1u);
        }

        // zero-fill tiles of this chunk above the diagonal band
        const int z_lo = max(t_lo, 2 * qb + 2);
        for (int tg = z_lo; tg <= t_lo + 7; tg++) {
            #pragma unroll
            for (int i = 0; i < 16; i++) {
                const int idx = tid + (i << 7);
                const int rr = idx >> 4, c4 = idx & 15;
                *(float4*)(outp + (size_t)(q0 + rr) * TT + (tg << 6) + (c4 << 2)) =
                    make_float4(0.f, 0.f, 0.f, 0.f);
            }
        }
        return;
    }

    // =================== STORE PHASE ===================
    if (tid == 0) wait_flag(&g_flag[fidx], (unsigned)nchunks);
    __syncthreads();

    float inv0[2], inv1[2];
    float* or0[2]; float* or1[2];
    const float* pp = g_part + ((size_t)fidx << 9);
    #pragma unroll
    for (int r2 = 0; r2 < 2; r2++) {
        const int ra = lr[r2], rb = lr[r2] + 8;
        inv0[r2] = 1.0f / (pp[ra] + pp[128 + ra] + pp[256 + ra] + pp[384 + ra]);
        inv1[r2] = 1.0f / (pp[rb] + pp[128 + rb] + pp[256 + rb] + pp[384 + rb]);
        or0[r2] = outp + (size_t)grow0[r2] * TT;
        or1[r2] = outp + (size_t)grow1[r2] * TT;
    }

    #pragma unroll 1
    for (int i = 0; i < nm; i++) {
        CP_WAIT2();
        __syncthreads();
        const uint32_t stg = sb + ((uint32_t)(i % 3) << 14);
        const int tg = t_lo + i;
        const bool msk = (tg >= 2 * qb);
        #pragma unroll 1
        for (int nfp = 0; nfp < 4; nfp++) {
            float a00[4] = {0,0,0,0}, a01[4] = {0,0,0,0};
            float a10[4] = {0,0,0,0}, a11[4] = {0,0,0,0};
            const uint32_t nbase = stg + ((uint32_t)nfp << 11);
            mma_tile3(nbase, bOff, ah, al, a00, a01, a10, a11);

            const int c0 = (tg << 6) + (nfp << 4) + cbase;
            #pragma unroll
            for (int r2 = 0; r2 < 2; r2++) {
                float* accA = r2 ? a10 : a00;
                float* accB = r2 ? a11 : a01;
                float2 v;
                if (!msk) {
                    v.x = __expf(accA[0]) * inv0[r2]; v.y = __expf(accA[1]) * inv0[r2];
                    *(float2*)(or0[r2] + c0) = v;
                    v.x = __expf(accB[0]) * inv0[r2]; v.y = __expf(accB[1]) * inv0[r2];
                    *(float2*)(or0[r2] + c0 + 8) = v;
                    v.x = __expf(accA[2]) * inv1[r2]; v.y = __expf(accA[3]) * inv1[r2];
                    *(float2*)(or1[r2] + c0) = v;
                    v.x = __expf(accB[2]) * inv1[r2]; v.y = __expf(accB[3]) * inv1[r2];
                    *(float2*)(or1[r2] + c0 + 8) = v;
                } else {
                    v.x = (c0     <= grow0[r2]) ? __expf(accA[0]) * inv0[r2] : 0.f;
                    v.y = (c0 + 1 <= grow0[r2]) ? __expf(accA[1]) * inv0[r2] : 0.f;
                    *(float2*)(or0[r2] + c0) = v;
                    v.x = (c0 + 8 <= grow0[r2]) ? __expf(accB[0]) * inv0[r2] : 0.f;
                    v.y = (c0 + 9 <= grow0[r2]) ? __expf(accB[1]) * inv0[r2] : 0.f;
                    *(float2*)(or0[r2] + c0 + 8) = v;
                    v.x = (c0     <= grow1[r2]) ? __expf(accA[2]) * inv1[r2] : 0.f;
                    v.y = (c0 + 1 <= grow1[r2]) ? __expf(accA[3]) * inv1[r2] : 0.f;
                    *(float2*)(or1[r2] + c0) = v;
                    v.x = (c0 + 8 <= grow1[r2]) ? __expf(accB[2]) * inv1[r2] : 0.f;
                    v.y = (c0 + 9 <= grow1[r2]) ? __expf(accB[3]) * inv1[r2] : 0.f;
                    *(float2*)(or1[r2] + c0 + 8) = v;
                }
            }
        }
        __syncthreads();
        if (i + 3 < nm) issue_tile(sb, (i + 3) % 3, kb + ((size_t)(i + 3) << 14), tid, true);
        CP_COMMIT();
    }
}

extern "C" void kernel_launch(void* const* d_in, const int* in_sizes, int n_in,
                              void* d_out, int out_size)
{
    const float* q = (const float*)d_in[0];
    const float* k = (const float*)d_in[1];
    float* out = (float*)d_out;

    reset_flags<<<1, 256>>>();

    cudaFuncSetAttribute(sdp_mega,
                         cudaFuncAttributeMaxDynamicSharedMemorySize, SMEM_BYTES);
    // [0,768) prep_q | [768,1536) prep_k | [1536,4608) sum | [4608,7680) store
    sdp_mega<<<7680, 128, SMEM_BYTES>>>(q, k, out);
}

// round 11
// speedup vs baseline: 1.5070x; 1.5070x over previous
#include <cuda_runtime.h>
#include <cuda_bf16.h>
#include <cstdint>

// causal softmax(QK^T/sqrt(64)): q,k [48,2048,64] fp32 -> out [48,2048,2048] fp32
//
// prep_all (ONE launch, bid-split):
//   [0,768)    q -> bf16 hi/lo A-FRAGMENT-layout scratch; zero partials+flags
//   [768,2304) k -> bf16 hi/lo swizzled smem-image tile scratch
// sdp_fused: phase in blockIdx.z:
//   z <  48 (sum, dispatched first): MMA (1-split bf16 qb>=1 / 3-split qb==0)
//     + exp -> partial row sums; post flag (release); upper-triangle zero-fill.
//   z >= 48 (store): prefetch K + A frags, spin (acquire) on flag, 3-split MMA,
//     exp, normalize, coalesced stores.
// Deadlock-free: in-order dispatch; sum CTAs never wait.

#define TT 2048
#define NBH 48

__device__ __align__(16) char g_qf[(size_t)NBH * 16 * 32768];  // [bh][qb]: hi 16KB | lo 16KB
__device__ __align__(16) char g_ki[(size_t)NBH * 32 * 16384];  // [bh][t64]: hi 8KB | lo 8KB
__device__ float g_part[NBH * 16 * 4 * 128];                   // [bh][qb][chunk][row]
__device__ unsigned g_flag[NBH * 16];                          // completed chunks per (bh,qb)

#define SMEM_BYTES (3 * 16384)

__device__ __forceinline__ uint32_t smem_u32(const void* p) {
    uint32_t a;
    asm("{ .reg .u64 t; cvta.to.shared.u64 t, %1; cvt.u32.u64 %0, t; }" : "=r"(a) : "l"(p));
    return a;
}
__device__ __forceinline__ void ldsm_x4(uint32_t r[4], uint32_t addr) {
    asm volatile("ldmatrix.sync.aligned.m8n8.x4.shared.b16 {%0,%1,%2,%3}, [%4];"
        : "=r"(r[0]), "=r"(r[1]), "=r"(r[2]), "=r"(r[3]) : "r"(addr));
}
__device__ __forceinline__ void mma16816(float c[4], const uint32_t a[4], const uint32_t b[2]) {
    asm volatile("mma.sync.aligned.m16n8k16.row.col.f32.bf16.bf16.f32 "
        "{%0,%1,%2,%3}, {%4,%5,%6,%7}, {%8,%9}, {%0,%1,%2,%3};"
        : "+f"(c[0]), "+f"(c[1]), "+f"(c[2]), "+f"(c[3])
        : "r"(a[0]), "r"(a[1]), "r"(a[2]), "r"(a[3]), "r"(b[0]), "r"(b[1]));
}
#define CP_ASYNC16(sa, gp) \
    asm volatile("cp.async.cg.shared.global [%0], [%1], 16;" :: "r"(sa), "l"(gp))
#define CP_COMMIT() asm volatile("cp.async.commit_group;")
#define CP_WAIT2()  asm volatile("cp.async.wait_group 2;")

__device__ __forceinline__ void split2(float x, float y, uint32_t& h, uint32_t& l) {
    __nv_bfloat16 hx = __float2bfloat16(x);
    __nv_bfloat16 hy = __float2bfloat16(y);
    __nv_bfloat162 hv; hv.x = hx; hv.y = hy;
    __nv_bfloat162 lv;
    lv.x = __float2bfloat16(x - __bfloat162float(hx));
    lv.y = __float2bfloat16(y - __bfloat162float(hy));
    h = *reinterpret_cast<uint32_t*>(&hv);
    l = *reinterpret_cast<uint32_t*>(&lv);
}

// ---------------- prep_all: q-frag prep [0,768) | k tile prep [768,2304) ----------------
__global__ void __launch_bounds__(128)
prep_all(const float* __restrict__ qg, const float* __restrict__ kg)
{
    extern __shared__ char sm[];
    const int tid = threadIdx.x, w = tid >> 5, lane = tid & 31;
    int bid = (int)blockIdx.x;

    if (bid < 768) {
        const int qb = bid & 15, bh = bid >> 4;
        {
            const int base = ((bh << 4) + qb) << 9;
            #pragma unroll
            for (int j = 0; j < 4; j++) g_part[base + (j << 7) + tid] = 0.0f;
            if (tid == 0) g_flag[(bh << 4) + qb] = 0u;
        }

        const float* qptr = qg + ((size_t)bh * TT + (qb << 7)) * 64;
        #pragma unroll
        for (int i = 0; i < 8; i++) {
            const int idx = tid + (i << 7);
            const int r = idx >> 3, c = idx & 7;
            const float* p = qptr + r * 64 + (c << 3);
            float4 v0 = *(const float4*)p;
            float4 v1 = *(const float4*)(p + 4);
            v0.x *= 0.125f; v0.y *= 0.125f; v0.z *= 0.125f; v0.w *= 0.125f;
            v1.x *= 0.125f; v1.y *= 0.125f; v1.z *= 0.125f; v1.w *= 0.125f;
            uint4 h, l;
            split2(v0.x, v0.y, h.x, l.x);
            split2(v0.z, v0.w, h.y, l.y);
            split2(v1.x, v1.y, h.z, l.z);
            split2(v1.z, v1.w, h.w, l.w);
            const uint32_t off = (r << 7) + (((uint32_t)c ^ (r & 7)) << 4);
            *(uint4*)(sm + off) = h;
            *(uint4*)(sm + 16384 + off) = l;
        }
        __syncthreads();

        const uint32_t sb = smem_u32(sm);
        uint32_t ah[2][4][4], al[2][4][4];
        const int cpar = lane >> 4;
        #pragma unroll
        for (int r2 = 0; r2 < 2; r2++) {
            const int rA = (w << 5) + (r2 << 4) + (lane & 15);
            #pragma unroll
            for (int kc = 0; kc < 4; kc++) {
                const uint32_t off = (uint32_t)(rA << 7)
                                   + (((uint32_t)((kc << 1) + cpar) ^ (rA & 7)) << 4);
                ldsm_x4(ah[r2][kc], sb + off);
                ldsm_x4(al[r2][kc], sb + 16384 + off);
            }
        }
        char* dst = g_qf + ((size_t)((bh << 4) + qb) << 15);
        #pragma unroll
        for (int r2 = 0; r2 < 2; r2++) {
            const int g = (w << 1) + r2;
            #pragma unroll
            for (int kc = 0; kc < 4; kc++) {
                const uint32_t a = (uint32_t)(((((g << 2) + kc) << 5) + lane) << 4);
                *(uint4*)(dst + a) =
                    make_uint4(ah[r2][kc][0], ah[r2][kc][1], ah[r2][kc][2], ah[r2][kc][3]);
                *(uint4*)(dst + 16384 + a) =
                    make_uint4(al[r2][kc][0], al[r2][kc][1], al[r2][kc][2], al[r2][kc][3]);
            }
        }
        return;
    }

    // ---- k prep: 1536 CTAs x 512 chunks/CTA covers 786432 chunks ----
    bid -= 768;
    #pragma unroll
    for (int j = 0; j < 4; j++) {
        const int idx = (bid << 9) + (j << 7) + tid;
        const int kgr = idx >> 3;
        const int c   = idx & 7;
        const float* p = kg + (size_t)kgr * 64 + (c << 3);
        const float4 v0 = *(const float4*)p;
        const float4 v1 = *(const float4*)(p + 4);
        uint4 h, l;
        split2(v0.x, v0.y, h.x, l.x);
        split2(v0.z, v0.w, h.y, l.y);
        split2(v1.x, v1.y, h.z, l.z);
        split2(v1.z, v1.w, h.w, l.w);
        const uint32_t t64 = (uint32_t)kgr >> 6;
        const uint32_t row = (uint32_t)kgr & 63;
        const size_t off = ((size_t)t64 << 14) + row * 128 + (((uint32_t)c ^ (row & 7)) << 4);
        *(uint4*)(g_ki + off) = h;
        *(uint4*)(g_ki + off + 8192) = l;
    }
}

// ---------------- shared machinery ----------------
__device__ __forceinline__ void load_afrags(const char* src, int w, int lane, bool with_lo,
                                            uint32_t ah[2][4][4], uint32_t al[2][4][4])
{
    #pragma unroll
    for (int r2 = 0; r2 < 2; r2++) {
        const int g = (w << 1) + r2;
        #pragma unroll
        for (int kc = 0; kc < 4; kc++) {
            const uint32_t a = (uint32_t)(((((g << 2) + kc) << 5) + lane) << 4);
            const uint4 h = *(const uint4*)(src + a);
            ah[r2][kc][0] = h.x; ah[r2][kc][1] = h.y; ah[r2][kc][2] = h.z; ah[r2][kc][3] = h.w;
            if (with_lo) {
                const uint4 l = *(const uint4*)(src + 16384 + a);
                al[r2][kc][0] = l.x; al[r2][kc][1] = l.y; al[r2][kc][2] = l.z; al[r2][kc][3] = l.w;
            }
        }
    }
}

__device__ __forceinline__ void issue_tile(uint32_t sb, int stage, const char* src,
                                           int tid, bool with_lo)
{
    const uint32_t dst = sb + ((uint32_t)stage << 14) + ((uint32_t)tid << 4);
    const char* s = src + (tid << 4);
    #pragma unroll
    for (int i = 0; i < 4; i++)
        CP_ASYNC16(dst + (i << 11), s + (i << 11));
    if (with_lo) {
        #pragma unroll
        for (int i = 4; i < 8; i++)
            CP_ASYNC16(dst + (i << 11), s + (i << 11));
    }
}

__device__ __forceinline__ void mma_tile3(uint32_t nbase, const uint32_t bOff[4],
                                          const uint32_t ah[2][4][4], const uint32_t al[2][4][4],
                                          float a00[4], float a01[4], float a10[4], float a11[4])
{
    #pragma unroll
    for (int kc = 0; kc < 4; kc++) {
        uint32_t bhr[4], blr[4];
        ldsm_x4(bhr, nbase + bOff[kc]);
        ldsm_x4(blr, nbase + 8192 + bOff[kc]);
        mma16816(a00, ah[0][kc], &bhr[0]);
        mma16816(a01, ah[0][kc], &bhr[2]);
        mma16816(a10, ah[1][kc], &bhr[0]);
        mma16816(a11, ah[1][kc], &bhr[2]);
        mma16816(a00, ah[0][kc], &blr[0]);
        mma16816(a01, ah[0][kc], &blr[2]);
        mma16816(a10, ah[1][kc], &blr[0]);
        mma16816(a11, ah[1][kc], &blr[2]);
        mma16816(a00, al[0][kc], &bhr[0]);
        mma16816(a01, al[0][kc], &bhr[2]);
        mma16816(a10, al[1][kc], &bhr[0]);
        mma16816(a11, al[1][kc], &bhr[2]);
    }
}

__device__ __forceinline__ void mma_tile1(uint32_t nbase, const uint32_t bOff[4],
                                          const uint32_t ah[2][4][4],
                                          float a00[4], float a01[4], float a10[4], float a11[4])
{
    #pragma unroll
    for (int kc = 0; kc < 4; kc++) {
        uint32_t bhr[4];
        ldsm_x4(bhr, nbase + bOff[kc]);
        mma16816(a00, ah[0][kc], &bhr[0]);
        mma16816(a01, ah[0][kc], &bhr[2]);
        mma16816(a10, ah[1][kc], &bhr[0]);
        mma16816(a11, ah[1][kc], &bhr[2]);
    }
}

// ---------------- fused sum+store kernel ----------------
__global__ void __launch_bounds__(128, 4)
sdp_fused(float* __restrict__ outg)
{
    extern __shared__ char smem[];
    const uint32_t sb = smem_u32(smem);
    const int tid = threadIdx.x, w = tid >> 5, lane = tid & 31;
    const int ch = blockIdx.x;
    const int qb = 15 - (int)blockIdx.y;
    const bool is_store = (blockIdx.z >= NBH);
    const int bh = (int)blockIdx.z - (is_store ? NBH : 0);
    const int t_lo = ch << 3;
    const int dlim = 2 * qb + 1;
    const int q0 = qb << 7;
    const int nchunks = (dlim >> 3) + 1;
    const int fidx = (bh << 4) + qb;
    float* outp = outg + (size_t)bh * TT * TT;

    if (is_store && t_lo > dlim) return;

    const bool has_mma = (t_lo <= dlim);
    const int t_hi = min(t_lo + 7, dlim);
    const int nm = has_mma ? (t_hi - t_lo + 1) : 0;
    const bool full = is_store || (qb == 0);

    uint32_t ah[2][4][4], al[2][4][4];
    const int rowB  = (lane & 7) + ((lane >> 4) << 3);
    const int cparB = (lane >> 3) & 1;
    uint32_t bOff[4];
    #pragma unroll
    for (int kc = 0; kc < 4; kc++)
        bOff[kc] = (uint32_t)(rowB << 7)
                 + (((uint32_t)((kc << 1) + cparB) ^ (rowB & 7)) << 4);
    const int cbase = (lane & 3) << 1;
    int lr[2], grow0[2], grow1[2];
    #pragma unroll
    for (int r2 = 0; r2 < 2; r2++) {
        lr[r2] = (w << 5) + (r2 << 4) + (lane >> 2);
        grow0[r2] = q0 + lr[r2];
        grow1[r2] = grow0[r2] + 8;
    }

    const char* kb = g_ki + ((size_t)(bh * 32 + t_lo) << 14);

    if (has_mma) {
        load_afrags(g_qf + ((size_t)fidx << 15), w, lane, full, ah, al);
        #pragma unroll
        for (int p = 0; p < 3; p++) {
            if (p < nm) issue_tile(sb, p, kb + ((size_t)p << 14), tid, full);
            CP_COMMIT();
        }
    }

    if (!is_store) {
        // =================== SUM PHASE ===================
        if (has_mma) {
            float s0[2] = {0.f, 0.f}, s1[2] = {0.f, 0.f};
            #pragma unroll 1
            for (int i = 0; i < nm; i++) {
                CP_WAIT2();
                __syncthreads();
                const uint32_t stg = sb + ((uint32_t)(i % 3) << 14);
                const int tg = t_lo + i;
                const bool msk = (tg >= 2 * qb);
                #pragma unroll 1
                for (int nfp = 0; nfp < 4; nfp++) {
                    float a00[4] = {0,0,0,0}, a01[4] = {0,0,0,0};
                    float a10[4] = {0,0,0,0}, a11[4] = {0,0,0,0};
                    const uint32_t nbase = stg + ((uint32_t)nfp << 11);
                    if (full) mma_tile3(nbase, bOff, ah, al, a00, a01, a10, a11);
                    else      mma_tile1(nbase, bOff, ah,     a00, a01, a10, a11);

                    const int c0 = (tg << 6) + (nfp << 4) + cbase;
                    #pragma unroll
                    for (int r2 = 0; r2 < 2; r2++) {
                        float* accA = r2 ? a10 : a00;
                        float* accB = r2 ? a11 : a01;
                        if (!msk) {
                            s0[r2] += __expf(accA[0]) + __expf(accA[1])
                                    + __expf(accB[0]) + __expf(accB[1]);
                            s1[r2] += __expf(accA[2]) + __expf(accA[3])
                                    + __expf(accB[2]) + __expf(accB[3]);
                        } else {
                            if (c0     <= grow0[r2]) s0[r2] += __expf(accA[0]);
                            if (c0 + 1 <= grow0[r2]) s0[r2] += __expf(accA[1]);
                            if (c0 + 8 <= grow0[r2]) s0[r2] += __expf(accB[0]);
                            if (c0 + 9 <= grow0[r2]) s0[r2] += __expf(accB[1]);
                            if (c0     <= grow1[r2]) s1[r2] += __expf(accA[2]);
                            if (c0 + 1 <= grow1[r2]) s1[r2] += __expf(accA[3]);
                            if (c0 + 8 <= grow1[r2]) s1[r2] += __expf(accB[2]);
                            if (c0 + 9 <= grow1[r2]) s1[r2] += __expf(accB[3]);
                        }
                    }
                }
                __syncthreads();
                if (i + 3 < nm) issue_tile(sb, (i + 3) % 3, kb + ((size_t)(i + 3) << 14), tid, full);
                CP_COMMIT();
            }

            #pragma unroll
            for (int r2 = 0; r2 < 2; r2++) {
                s0[r2] += __shfl_xor_sync(0xffffffffu, s0[r2], 1);
                s0[r2] += __shfl_xor_sync(0xffffffffu, s0[r2], 2);
                s1[r2] += __shfl_xor_sync(0xffffffffu, s1[r2], 1);
                s1[r2] += __shfl_xor_sync(0xffffffffu, s1[r2], 2);
            }
            if ((lane & 3) == 0) {
                float* pp = g_part + (size_t)(((fidx << 2) + ch) << 7);
                #pragma unroll
                for (int r2 = 0; r2 < 2; r2++) {
                    pp[lr[r2]]     = s0[r2];
                    pp[lr[r2] + 8] = s1[r2];
                }
            }
            __threadfence();
            __syncthreads();
            if (tid == 0) atomicAdd(&g_flag[fidx], 1u);
        }

        // zero-fill tiles of this chunk above the diagonal band
        const int z_lo = max(t_lo, 2 * qb + 2);
        for (int tg = z_lo; tg <= t_lo + 7; tg++) {
            #pragma unroll
            for (int i = 0; i < 16; i++) {
                const int idx = tid + (i << 7);
                const int rr = idx >> 4, c4 = idx & 15;
                *(float4*)(outp + (size_t)(q0 + rr) * TT + (tg << 6) + (c4 << 2)) =
                    make_float4(0.f, 0.f, 0.f, 0.f);
            }
        }
        return;
    }

    // =================== STORE PHASE ===================
    if (tid == 0) {
        unsigned v;
        do {
            asm volatile("ld.acquire.gpu.global.b32 %0, [%1];"
                         : "=r"(v) : "l"(&g_flag[fidx]) : "memory");
            if ((int)v >= nchunks) break;
            __nanosleep(128);
        } while (true);
    }
    __syncthreads();

    float inv0[2], inv1[2];
    float* or0[2]; float* or1[2];
    const float* pp = g_part + ((size_t)fidx << 9);
    #pragma unroll
    for (int r2 = 0; r2 < 2; r2++) {
        const int ra = lr[r2], rb = lr[r2] + 8;
        inv0[r2] = 1.0f / (pp[ra] + pp[128 + ra] + pp[256 + ra] + pp[384 + ra]);
        inv1[r2] = 1.0f / (pp[rb] + pp[128 + rb] + pp[256 + rb] + pp[384 + rb]);
        or0[r2] = outp + (size_t)grow0[r2] * TT;
        or1[r2] = outp + (size_t)grow1[r2] * TT;
    }

    #pragma unroll 1
    for (int i = 0; i < nm; i++) {
        CP_WAIT2();
        __syncthreads();
        const uint32_t stg = sb + ((uint32_t)(i % 3) << 14);
        const int tg = t_lo + i;
        const bool msk = (tg >= 2 * qb);
        #pragma unroll 1
        for (int nfp = 0; nfp < 4; nfp++) {
            float a00[4] = {0,0,0,0}, a01[4] = {0,0,0,0};
            float a10[4] = {0,0,0,0}, a11[4] = {0,0,0,0};
            const uint32_t nbase = stg + ((uint32_t)nfp << 11);
            mma_tile3(nbase, bOff, ah, al, a00, a01, a10, a11);

            const int c0 = (tg << 6) + (nfp << 4) + cbase;
            #pragma unroll
            for (int r2 = 0; r2 < 2; r2++) {
                float* accA = r2 ? a10 : a00;
                float* accB = r2 ? a11 : a01;
                float2 v;
                if (!msk) {
                    v.x = __expf(accA[0]) * inv0[r2]; v.y = __expf(accA[1]) * inv0[r2];
                    *(float2*)(or0[r2] + c0) = v;
                    v.x = __expf(accB[0]) * inv0[r2]; v.y = __expf(accB[1]) * inv0[r2];
                    *(float2*)(or0[r2] + c0 + 8) = v;
                    v.x = __expf(accA[2]) * inv1[r2]; v.y = __expf(accA[3]) * inv1[r2];
                    *(float2*)(or1[r2] + c0) = v;
                    v.x = __expf(accB[2]) * inv1[r2]; v.y = __expf(accB[3]) * inv1[r2];
                    *(float2*)(or1[r2] + c0 + 8) = v;
                } else {
                    v.x = (c0     <= grow0[r2]) ? __expf(accA[0]) * inv0[r2] : 0.f;
                    v.y = (c0 + 1 <= grow0[r2]) ? __expf(accA[1]) * inv0[r2] : 0.f;
                    *(float2*)(or0[r2] + c0) = v;
                    v.x = (c0 + 8 <= grow0[r2]) ? __expf(accB[0]) * inv0[r2] : 0.f;
                    v.y = (c0 + 9 <= grow0[r2]) ? __expf(accB[1]) * inv0[r2] : 0.f;
                    *(float2*)(or0[r2] + c0 + 8) = v;
                    v.x = (c0     <= grow1[r2]) ? __expf(accA[2]) * inv1[r2] : 0.f;
                    v.y = (c0 + 1 <= grow1[r2]) ? __expf(accA[3]) * inv1[r2] : 0.f;
                    *(float2*)(or1[r2] + c0) = v;
                    v.x = (c0 + 8 <= grow1[r2]) ? __expf(accB[2]) * inv1[r2] : 0.f;
                    v.y = (c0 + 9 <= grow1[r2]) ? __expf(accB[3]) * inv1[r2] : 0.f;
                    *(float2*)(or1[r2] + c0 + 8) = v;
                }
            }
        }
        __syncthreads();
        if (i + 3 < nm) issue_tile(sb, (i + 3) % 3, kb + ((size_t)(i + 3) << 14), tid, true);
        CP_COMMIT();
    }
}

extern "C" void kernel_launch(void* const* d_in, const int* in_sizes, int n_in,
                              void* d_out, int out_size)
{
    const float* q = (const float*)d_in[0];
    const float* k = (const float*)d_in[1];
    float* out = (float*)d_out;

    // merged prep: [0,768) q-frag prep, [768,2304) k tile prep
    prep_all<<<2304, 128, 32768>>>(q, k);

    cudaFuncSetAttribute(sdp_fused,
                         cudaFuncAttributeMaxDynamicSharedMemorySize, SMEM_BYTES);
    // z < 48: sum CTAs (dispatched first), z >= 48: store CTAs
    sdp_fused<<<dim3(4, 16, 2 * NBH), 128, SMEM_BYTES>>>(out);
}

// round 12
// speedup vs baseline: 1.5486x; 1.0276x over previous
#include <cuda_runtime.h>
#include <cuda_bf16.h>
#include <cstdint>

// causal softmax(QK^T/sqrt(64)): q,k [48,2048,64] fp32 -> out [48,2048,2048] fp32
//
// prep_all (ONE launch, bid-split):
//   [0,768)    q -> bf16 hi/lo A-FRAGMENT-layout scratch; zero partials+flags
//   [768,2304) k -> bf16 hi/lo swizzled smem-image tile scratch
// sdp_fused: phase in blockIdx.z:
//   z <  48 (sum, dispatched first): MMA (1-split bf16 qb>=1 / 3-split qb==0)
//     + exp -> partial row sums; post flag (release); upper-triangle zero-fill.
//   z >= 48 (store): prefetch K + A frags, spin (acquire) on flag, 3-split MMA,
//     exp, normalize, coalesced stores.
// All output stores use __stcs (evict-first streaming) so the write-once output
// doesn't evict the K-scratch / q-frag working set from L2.

#define TT 2048
#define NBH 48

__device__ __align__(16) char g_qf[(size_t)NBH * 16 * 32768];  // [bh][qb]: hi 16KB | lo 16KB
__device__ __align__(16) char g_ki[(size_t)NBH * 32 * 16384];  // [bh][t64]: hi 8KB | lo 8KB
__device__ float g_part[NBH * 16 * 4 * 128];                   // [bh][qb][chunk][row]
__device__ unsigned g_flag[NBH * 16];                          // completed chunks per (bh,qb)

#define SMEM_BYTES (3 * 16384)

__device__ __forceinline__ uint32_t smem_u32(const void* p) {
    uint32_t a;
    asm("{ .reg .u64 t; cvta.to.shared.u64 t, %1; cvt.u32.u64 %0, t; }" : "=r"(a) : "l"(p));
    return a;
}
__device__ __forceinline__ void ldsm_x4(uint32_t r[4], uint32_t addr) {
    asm volatile("ldmatrix.sync.aligned.m8n8.x4.shared.b16 {%0,%1,%2,%3}, [%4];"
        : "=r"(r[0]), "=r"(r[1]), "=r"(r[2]), "=r"(r[3]) : "r"(addr));
}
__device__ __forceinline__ void mma16816(float c[4], const uint32_t a[4], const uint32_t b[2]) {
    asm volatile("mma.sync.aligned.m16n8k16.row.col.f32.bf16.bf16.f32 "
        "{%0,%1,%2,%3}, {%4,%5,%6,%7}, {%8,%9}, {%0,%1,%2,%3};"
        : "+f"(c[0]), "+f"(c[1]), "+f"(c[2]), "+f"(c[3])
        : "r"(a[0]), "r"(a[1]), "r"(a[2]), "r"(a[3]), "r"(b[0]), "r"(b[1]));
}
#define CP_ASYNC16(sa, gp) \
    asm volatile("cp.async.cg.shared.global [%0], [%1], 16;" :: "r"(sa), "l"(gp))
#define CP_COMMIT() asm volatile("cp.async.commit_group;")
#define CP_WAIT2()  asm volatile("cp.async.wait_group 2;")

__device__ __forceinline__ void split2(float x, float y, uint32_t& h, uint32_t& l) {
    __nv_bfloat16 hx = __float2bfloat16(x);
    __nv_bfloat16 hy = __float2bfloat16(y);
    __nv_bfloat162 hv; hv.x = hx; hv.y = hy;
    __nv_bfloat162 lv;
    lv.x = __float2bfloat16(x - __bfloat162float(hx));
    lv.y = __float2bfloat16(y - __bfloat162float(hy));
    h = *reinterpret_cast<uint32_t*>(&hv);
    l = *reinterpret_cast<uint32_t*>(&lv);
}

// ---------------- prep_all: q-frag prep [0,768) | k tile prep [768,2304) ----------------
__global__ void __launch_bounds__(128)
prep_all(const float* __restrict__ qg, const float* __restrict__ kg)
{
    extern __shared__ char sm[];
    const int tid = threadIdx.x, w = tid >> 5, lane = tid & 31;
    int bid = (int)blockIdx.x;

    if (bid < 768) {
        const int qb = bid & 15, bh = bid >> 4;
        {
            const int base = ((bh << 4) + qb) << 9;
            #pragma unroll
            for (int j = 0; j < 4; j++) g_part[base + (j << 7) + tid] = 0.0f;
            if (tid == 0) g_flag[(bh << 4) + qb] = 0u;
        }

        const float* qptr = qg + ((size_t)bh * TT + (qb << 7)) * 64;
        #pragma unroll
        for (int i = 0; i < 8; i++) {
            const int idx = tid + (i << 7);
            const int r = idx >> 3, c = idx & 7;
            const float* p = qptr + r * 64 + (c << 3);
            float4 v0 = *(const float4*)p;
            float4 v1 = *(const float4*)(p + 4);
            v0.x *= 0.125f; v0.y *= 0.125f; v0.z *= 0.125f; v0.w *= 0.125f;
            v1.x *= 0.125f; v1.y *= 0.125f; v1.z *= 0.125f; v1.w *= 0.125f;
            uint4 h, l;
            split2(v0.x, v0.y, h.x, l.x);
            split2(v0.z, v0.w, h.y, l.y);
            split2(v1.x, v1.y, h.z, l.z);
            split2(v1.z, v1.w, h.w, l.w);
            const uint32_t off = (r << 7) + (((uint32_t)c ^ (r & 7)) << 4);
            *(uint4*)(sm + off) = h;
            *(uint4*)(sm + 16384 + off) = l;
        }
        __syncthreads();

        const uint32_t sb = smem_u32(sm);
        uint32_t ah[2][4][4], al[2][4][4];
        const int cpar = lane >> 4;
        #pragma unroll
        for (int r2 = 0; r2 < 2; r2++) {
            const int rA = (w << 5) + (r2 << 4) + (lane & 15);
            #pragma unroll
            for (int kc = 0; kc < 4; kc++) {
                const uint32_t off = (uint32_t)(rA << 7)
                                   + (((uint32_t)((kc << 1) + cpar) ^ (rA & 7)) << 4);
                ldsm_x4(ah[r2][kc], sb + off);
                ldsm_x4(al[r2][kc], sb + 16384 + off);
            }
        }
        char* dst = g_qf + ((size_t)((bh << 4) + qb) << 15);
        #pragma unroll
        for (int r2 = 0; r2 < 2; r2++) {
            const int g = (w << 1) + r2;
            #pragma unroll
            for (int kc = 0; kc < 4; kc++) {
                const uint32_t a = (uint32_t)(((((g << 2) + kc) << 5) + lane) << 4);
                *(uint4*)(dst + a) =
                    make_uint4(ah[r2][kc][0], ah[r2][kc][1], ah[r2][kc][2], ah[r2][kc][3]);
                *(uint4*)(dst + 16384 + a) =
                    make_uint4(al[r2][kc][0], al[r2][kc][1], al[r2][kc][2], al[r2][kc][3]);
            }
        }
        return;
    }

    // ---- k prep: 1536 CTAs x 512 chunks/CTA covers 786432 chunks ----
    bid -= 768;
    #pragma unroll
    for (int j = 0; j < 4; j++) {
        const int idx = (bid << 9) + (j << 7) + tid;
        const int kgr = idx >> 3;
        const int c   = idx & 7;
        const float* p = kg + (size_t)kgr * 64 + (c << 3);
        const float4 v0 = *(const float4*)p;
        const float4 v1 = *(const float4*)(p + 4);
        uint4 h, l;
        split2(v0.x, v0.y, h.x, l.x);
        split2(v0.z, v0.w, h.y, l.y);
        split2(v1.x, v1.y, h.z, l.z);
        split2(v1.z, v1.w, h.w, l.w);
        const uint32_t t64 = (uint32_t)kgr >> 6;
        const uint32_t row = (uint32_t)kgr & 63;
        const size_t off = ((size_t)t64 << 14) + row * 128 + (((uint32_t)c ^ (row & 7)) << 4);
        *(uint4*)(g_ki + off) = h;
        *(uint4*)(g_ki + off + 8192) = l;
    }
}

// ---------------- shared machinery ----------------
__device__ __forceinline__ void load_afrags(const char* src, int w, int lane, bool with_lo,
                                            uint32_t ah[2][4][4], uint32_t al[2][4][4])
{
    #pragma unroll
    for (int r2 = 0; r2 < 2; r2++) {
        const int g = (w << 1) + r2;
        #pragma unroll
        for (int kc = 0; kc < 4; kc++) {
            const uint32_t a = (uint32_t)(((((g << 2) + kc) << 5) + lane) << 4);
            const uint4 h = *(const uint4*)(src + a);
            ah[r2][kc][0] = h.x; ah[r2][kc][1] = h.y; ah[r2][kc][2] = h.z; ah[r2][kc][3] = h.w;
            if (with_lo) {
                const uint4 l = *(const uint4*)(src + 16384 + a);
                al[r2][kc][0] = l.x; al[r2][kc][1] = l.y; al[r2][kc][2] = l.z; al[r2][kc][3] = l.w;
            }
        }
    }
}

__device__ __forceinline__ void issue_tile(uint32_t sb, int stage, const char* src,
                                           int tid, bool with_lo)
{
    const uint32_t dst = sb + ((uint32_t)stage << 14) + ((uint32_t)tid << 4);
    const char* s = src + (tid << 4);
    #pragma unroll
    for (int i = 0; i < 4; i++)
        CP_ASYNC16(dst + (i << 11), s + (i << 11));
    if (with_lo) {
        #pragma unroll
        for (int i = 4; i < 8; i++)
            CP_ASYNC16(dst + (i << 11), s + (i << 11));
    }
}

__device__ __forceinline__ void mma_tile3(uint32_t nbase, const uint32_t bOff[4],
                                          const uint32_t ah[2][4][4], const uint32_t al[2][4][4],
                                          float a00[4], float a01[4], float a10[4], float a11[4])
{
    #pragma unroll
    for (int kc = 0; kc < 4; kc++) {
        uint32_t bhr[4], blr[4];
        ldsm_x4(bhr, nbase + bOff[kc]);
        ldsm_x4(blr, nbase + 8192 + bOff[kc]);
        mma16816(a00, ah[0][kc], &bhr[0]);
        mma16816(a01, ah[0][kc], &bhr[2]);
        mma16816(a10, ah[1][kc], &bhr[0]);
        mma16816(a11, ah[1][kc], &bhr[2]);
        mma16816(a00, ah[0][kc], &blr[0]);
        mma16816(a01, ah[0][kc], &blr[2]);
        mma16816(a10, ah[1][kc], &blr[0]);
        mma16816(a11, ah[1][kc], &blr[2]);
        mma16816(a00, al[0][kc], &bhr[0]);
        mma16816(a01, al[0][kc], &bhr[2]);
        mma16816(a10, al[1][kc], &bhr[0]);
        mma16816(a11, al[1][kc], &bhr[2]);
    }
}

__device__ __forceinline__ void mma_tile1(uint32_t nbase, const uint32_t bOff[4],
                                          const uint32_t ah[2][4][4],
                                          float a00[4], float a01[4], float a10[4], float a11[4])
{
    #pragma unroll
    for (int kc = 0; kc < 4; kc++) {
        uint32_t bhr[4];
        ldsm_x4(bhr, nbase + bOff[kc]);
        mma16816(a00, ah[0][kc], &bhr[0]);
        mma16816(a01, ah[0][kc], &bhr[2]);
        mma16816(a10, ah[1][kc], &bhr[0]);
        mma16816(a11, ah[1][kc], &bhr[2]);
    }
}

// ---------------- fused sum+store kernel ----------------
__global__ void __launch_bounds__(128, 4)
sdp_fused(float* __restrict__ outg)
{
    extern __shared__ char smem[];
    const uint32_t sb = smem_u32(smem);
    const int tid = threadIdx.x, w = tid >> 5, lane = tid & 31;
    const int ch = blockIdx.x;
    const int qb = 15 - (int)blockIdx.y;
    const bool is_store = (blockIdx.z >= NBH);
    const int bh = (int)blockIdx.z - (is_store ? NBH : 0);
    const int t_lo = ch << 3;
    const int dlim = 2 * qb + 1;
    const int q0 = qb << 7;
    const int nchunks = (dlim >> 3) + 1;
    const int fidx = (bh << 4) + qb;
    float* outp = outg + (size_t)bh * TT * TT;

    if (is_store && t_lo > dlim) return;

    const bool has_mma = (t_lo <= dlim);
    const int t_hi = min(t_lo + 7, dlim);
    const int nm = has_mma ? (t_hi - t_lo + 1) : 0;
    const bool full = is_store || (qb == 0);

    uint32_t ah[2][4][4], al[2][4][4];
    const int rowB  = (lane & 7) + ((lane >> 4) << 3);
    const int cparB = (lane >> 3) & 1;
    uint32_t bOff[4];
    #pragma unroll
    for (int kc = 0; kc < 4; kc++)
        bOff[kc] = (uint32_t)(rowB << 7)
                 + (((uint32_t)((kc << 1) + cparB) ^ (rowB & 7)) << 4);
    const int cbase = (lane & 3) << 1;
    int lr[2], grow0[2], grow1[2];
    #pragma unroll
    for (int r2 = 0; r2 < 2; r2++) {
        lr[r2] = (w << 5) + (r2 << 4) + (lane >> 2);
        grow0[r2] = q0 + lr[r2];
        grow1[r2] = grow0[r2] + 8;
    }

    const char* kb = g_ki + ((size_t)(bh * 32 + t_lo) << 14);

    if (has_mma) {
        load_afrags(g_qf + ((size_t)fidx << 15), w, lane, full, ah, al);
        #pragma unroll
        for (int p = 0; p < 3; p++) {
            if (p < nm) issue_tile(sb, p, kb + ((size_t)p << 14), tid, full);
            CP_COMMIT();
        }
    }

    if (!is_store) {
        // =================== SUM PHASE ===================
        if (has_mma) {
            float s0[2] = {0.f, 0.f}, s1[2] = {0.f, 0.f};
            #pragma unroll 1
            for (int i = 0; i < nm; i++) {
                CP_WAIT2();
                __syncthreads();
                const uint32_t stg = sb + ((uint32_t)(i % 3) << 14);
                const int tg = t_lo + i;
                const bool msk = (tg >= 2 * qb);
                #pragma unroll 1
                for (int nfp = 0; nfp < 4; nfp++) {
                    float a00[4] = {0,0,0,0}, a01[4] = {0,0,0,0};
                    float a10[4] = {0,0,0,0}, a11[4] = {0,0,0,0};
                    const uint32_t nbase = stg + ((uint32_t)nfp << 11);
                    if (full) mma_tile3(nbase, bOff, ah, al, a00, a01, a10, a11);
                    else      mma_tile1(nbase, bOff, ah,     a00, a01, a10, a11);

                    const int c0 = (tg << 6) + (nfp << 4) + cbase;
                    #pragma unroll
                    for (int r2 = 0; r2 < 2; r2++) {
                        float* accA = r2 ? a10 : a00;
                        float* accB = r2 ? a11 : a01;
                        if (!msk) {
                            s0[r2] += __expf(accA[0]) + __expf(accA[1])
                                    + __expf(accB[0]) + __expf(accB[1]);
                            s1[r2] += __expf(accA[2]) + __expf(accA[3])
                                    + __expf(accB[2]) + __expf(accB[3]);
                        } else {
                            if (c0     <= grow0[r2]) s0[r2] += __expf(accA[0]);
                            if (c0 + 1 <= grow0[r2]) s0[r2] += __expf(accA[1]);
                            if (c0 + 8 <= grow0[r2]) s0[r2] += __expf(accB[0]);
                            if (c0 + 9 <= grow0[r2]) s0[r2] += __expf(accB[1]);
                            if (c0     <= grow1[r2]) s1[r2] += __expf(accA[2]);
                            if (c0 + 1 <= grow1[r2]) s1[r2] += __expf(accA[3]);
                            if (c0 + 8 <= grow1[r2]) s1[r2] += __expf(accB[2]);
                            if (c0 + 9 <= grow1[r2]) s1[r2] += __expf(accB[3]);
                        }
                    }
                }
                __syncthreads();
                if (i + 3 < nm) issue_tile(sb, (i + 3) % 3, kb + ((size_t)(i + 3) << 14), tid, full);
                CP_COMMIT();
            }

            #pragma unroll
            for (int r2 = 0; r2 < 2; r2++) {
                s0[r2] += __shfl_xor_sync(0xffffffffu, s0[r2], 1);
                s0[r2] += __shfl_xor_sync(0xffffffffu, s0[r2], 2);
                s1[r2] += __shfl_xor_sync(0xffffffffu, s1[r2], 1);
                s1[r2] += __shfl_xor_sync(0xffffffffu, s1[r2], 2);
            }
            if ((lane & 3) == 0) {
                float* pp = g_part + (size_t)(((fidx << 2) + ch) << 7);
                #pragma unroll
                for (int r2 = 0; r2 < 2; r2++) {
                    pp[lr[r2]]     = s0[r2];
                    pp[lr[r2] + 8] = s1[r2];
                }
            }
            __threadfence();
            __syncthreads();
            if (tid == 0) atomicAdd(&g_flag[fidx], 1u);
        }

        // zero-fill tiles of this chunk above the diagonal band (streaming stores)
        const int z_lo = max(t_lo, 2 * qb + 2);
        const float4 z4 = make_float4(0.f, 0.f, 0.f, 0.f);
        for (int tg = z_lo; tg <= t_lo + 7; tg++) {
            #pragma unroll
            for (int i = 0; i < 16; i++) {
                const int idx = tid + (i << 7);
                const int rr = idx >> 4, c4 = idx & 15;
                __stcs((float4*)(outp + (size_t)(q0 + rr) * TT + (tg << 6) + (c4 << 2)), z4);
            }
        }
        return;
    }

    // =================== STORE PHASE ===================
    if (tid == 0) {
        unsigned v;
        do {
            asm volatile("ld.acquire.gpu.global.b32 %0, [%1];"
                         : "=r"(v) : "l"(&g_flag[fidx]) : "memory");
            if ((int)v >= nchunks) break;
            __nanosleep(128);
        } while (true);
    }
    __syncthreads();

    float inv0[2], inv1[2];
    float* or0[2]; float* or1[2];
    const float* pp = g_part + ((size_t)fidx << 9);
    #pragma unroll
    for (int r2 = 0; r2 < 2; r2++) {
        const int ra = lr[r2], rb = lr[r2] + 8;
        inv0[r2] = 1.0f / (pp[ra] + pp[128 + ra] + pp[256 + ra] + pp[384 + ra]);
        inv1[r2] = 1.0f / (pp[rb] + pp[128 + rb] + pp[256 + rb] + pp[384 + rb]);
        or0[r2] = outp + (size_t)grow0[r2] * TT;
        or1[r2] = outp + (size_t)grow1[r2] * TT;
    }

    #pragma unroll 1
    for (int i = 0; i < nm; i++) {
        CP_WAIT2();
        __syncthreads();
        const uint32_t stg = sb + ((uint32_t)(i % 3) << 14);
        const int tg = t_lo + i;
        const bool msk = (tg >= 2 * qb);
        #pragma unroll 1
        for (int nfp = 0; nfp < 4; nfp++) {
            float a00[4] = {0,0,0,0}, a01[4] = {0,0,0,0};
            float a10[4] = {0,0,0,0}, a11[4] = {0,0,0,0};
            const uint32_t nbase = stg + ((uint32_t)nfp << 11);
            mma_tile3(nbase, bOff, ah, al, a00, a01, a10, a11);

            const int c0 = (tg << 6) + (nfp << 4) + cbase;
            #pragma unroll
            for (int r2 = 0; r2 < 2; r2++) {
                float* accA = r2 ? a10 : a00;
                float* accB = r2 ? a11 : a01;
                float2 v;
                if (!msk) {
                    v.x = __expf(accA[0]) * inv0[r2]; v.y = __expf(accA[1]) * inv0[r2];
                    __stcs((float2*)(or0[r2] + c0), v);
                    v.x = __expf(accB[0]) * inv0[r2]; v.y = __expf(accB[1]) * inv0[r2];
                    __stcs((float2*)(or0[r2] + c0 + 8), v);
                    v.x = __expf(accA[2]) * inv1[r2]; v.y = __expf(accA[3]) * inv1[r2];
                    __stcs((float2*)(or1[r2] + c0), v);
                    v.x = __expf(accB[2]) * inv1[r2]; v.y = __expf(accB[3]) * inv1[r2];
                    __stcs((float2*)(or1[r2] + c0 + 8), v);
                } else {
                    v.x = (c0     <= grow0[r2]) ? __expf(accA[0]) * inv0[r2] : 0.f;
                    v.y = (c0 + 1 <= grow0[r2]) ? __expf(accA[1]) * inv0[r2] : 0.f;
                    __stcs((float2*)(or0[r2] + c0), v);
                    v.x = (c0 + 8 <= grow0[r2]) ? __expf(accB[0]) * inv0[r2] : 0.f;
                    v.y = (c0 + 9 <= grow0[r2]) ? __expf(accB[1]) * inv0[r2] : 0.f;
                    __stcs((float2*)(or0[r2] + c0 + 8), v);
                    v.x = (c0     <= grow1[r2]) ? __expf(accA[2]) * inv1[r2] : 0.f;
                    v.y = (c0 + 1 <= grow1[r2]) ? __expf(accA[3]) * inv1[r2] : 0.f;
                    __stcs((float2*)(or1[r2] + c0), v);
                    v.x = (c0 + 8 <= grow1[r2]) ? __expf(accB[2]) * inv1[r2] : 0.f;
                    v.y = (c0 + 9 <= grow1[r2]) ? __expf(accB[3]) * inv1[r2] : 0.f;
                    __stcs((float2*)(or1[r2] + c0 + 8), v);
                }
            }
        }
        __syncthreads();
        if (i + 3 < nm) issue_tile(sb, (i + 3) % 3, kb + ((size_t)(i + 3) << 14), tid, true);
        CP_COMMIT();
    }
}

extern "C" void kernel_launch(void* const* d_in, const int* in_sizes, int n_in,
                              void* d_out, int out_size)
{
    const float* q = (const float*)d_in[0];
    const float* k = (const float*)d_in[1];
    float* out = (float*)d_out;

    // merged prep: [0,768) q-frag prep, [768,2304) k tile prep
    prep_all<<<2304, 128, 32768>>>(q, k);

    cudaFuncSetAttribute(sdp_fused,
                         cudaFuncAttributeMaxDynamicSharedMemorySize, SMEM_BYTES);
    // z < 48: sum CTAs (dispatched first), z >= 48: store CTAs
    sdp_fused<<<dim3(4, 16, 2 * NBH), 128, SMEM_BYTES>>>(out);
}